// round 2
// baseline (speedup 1.0000x reference)
#include <cuda_runtime.h>
#include <cuda_bf16.h>
#include <math.h>

// ---------------------------------------------------------------------------
// Problem constants
// ---------------------------------------------------------------------------
// b=4, n=4096, dim=1024, k_chunks=64, CS=64, CP=63, r=2, rlen=128
// bk = 256 chunks, L = 256 kv rows per chunk (+1 null), H=8, DH=64, inner=512
#define DIMM   1024
#define INNER  512
#define BK_CH  256          // bk = b * k_chunks
#define CSZ    64           // chunk size (queries per chunk)
#define LKV    256          // kv rows per chunk (r*rlen)
#define NH     8
#define DHD    64
#define MQ     (BK_CH*CSZ)      // 16384 rows of Q / O
#define MKV    (BK_CH*LKV)      // 65536 rows of K / V

// ---------------------------------------------------------------------------
// Scratch (device globals: no allocation allowed)
// ---------------------------------------------------------------------------
__device__ float g_Q[(size_t)MQ * INNER];
__device__ float g_K[(size_t)MKV * INNER];
__device__ float g_V[(size_t)MKV * INNER];
__device__ float g_O[(size_t)MQ * INNER];

// ---------------------------------------------------------------------------
// SGEMM: C[M,N] = A[M,K] @ W[K,N]
// BM=128, BN=128, BK=8, 256 threads, 8x8 micro-tile
// GATHER==1 : A row gm reads x[(gm+63)*K] if (gm%4096)<4033 else zeros
// EPI==1    : scatter row gm -> out[b*4096 + (gm%4096)+63] if (gm%4096)<4033,
//             adding bias[n]. EPI==0: plain store.
// ---------------------------------------------------------------------------
#define GBM 128
#define GBN 128
#define GBK 8

template<int GATHER, int EPI>
__global__ __launch_bounds__(256, 2)
void sgemm_kernel(const float* __restrict__ A, const float* __restrict__ W,
                  float* __restrict__ C, int M, int N, int K,
                  const float* __restrict__ bias)
{
    __shared__ float As[GBK][GBM];
    __shared__ float Bs[GBK][GBN];

    const int n0 = blockIdx.x * GBN;
    const int m0 = blockIdx.y * GBM;
    const int t  = threadIdx.x;

    const int arow = t >> 1;          // 0..127
    const int acol = (t & 1) * 4;     // 0 or 4
    const int brow = t >> 5;          // 0..7
    const int bcol = (t & 31) * 4;    // 0..124

    const int ty = t >> 4;            // 0..15
    const int tx = t & 15;            // 0..15

    // Resolve A row pointer (with optional shifted-x gather)
    const float* Aptr;
    bool avalid = true;
    {
        int gm = m0 + arow;
        if (GATHER == 1) {
            int pos = gm & 4095;
            if (pos < 4033) {
                Aptr = A + (size_t)(gm + 63) * K;
            } else {
                Aptr = A;           // never dereferenced
                avalid = false;
            }
        } else {
            Aptr = A + (size_t)gm * K;
        }
    }

    float acc[8][8];
    #pragma unroll
    for (int i = 0; i < 8; i++)
        #pragma unroll
        for (int j = 0; j < 8; j++) acc[i][j] = 0.f;

    for (int k0 = 0; k0 < K; k0 += GBK) {
        float4 av = make_float4(0.f, 0.f, 0.f, 0.f);
        if (avalid) av = *(const float4*)(Aptr + k0 + acol);
        float4 bv = *(const float4*)(W + (size_t)(k0 + brow) * N + n0 + bcol);

        __syncthreads();
        As[acol + 0][arow] = av.x;
        As[acol + 1][arow] = av.y;
        As[acol + 2][arow] = av.z;
        As[acol + 3][arow] = av.w;
        *(float4*)&Bs[brow][bcol] = bv;
        __syncthreads();

        #pragma unroll
        for (int kk = 0; kk < GBK; kk++) {
            float a[8], b[8];
            #pragma unroll
            for (int i = 0; i < 8; i++) a[i] = As[kk][ty * 8 + i];
            #pragma unroll
            for (int j = 0; j < 8; j++) b[j] = Bs[kk][tx * 8 + j];
            #pragma unroll
            for (int i = 0; i < 8; i++)
                #pragma unroll
                for (int j = 0; j < 8; j++)
                    acc[i][j] = fmaf(a[i], b[j], acc[i][j]);
        }
    }

    #pragma unroll
    for (int i = 0; i < 8; i++) {
        const int gm = m0 + ty * 8 + i;
        if (EPI == 0) {
            float* crow = C + (size_t)gm * N + n0 + tx * 8;
            #pragma unroll
            for (int j = 0; j < 8; j += 4) {
                *(float4*)(crow + j) =
                    make_float4(acc[i][j], acc[i][j+1], acc[i][j+2], acc[i][j+3]);
            }
        } else {
            const int pos = gm & 4095;
            if (pos < 4033) {
                const int bb = gm >> 12;
                float* crow = C + ((size_t)bb * 4096 + pos + 63) * N + n0 + tx * 8;
                const float* brow_ = bias + n0 + tx * 8;
                #pragma unroll
                for (int j = 0; j < 8; j += 4) {
                    float4 bv = *(const float4*)(brow_ + j);
                    *(float4*)(crow + j) =
                        make_float4(acc[i][j]   + bv.x, acc[i][j+1] + bv.y,
                                    acc[i][j+2] + bv.z, acc[i][j+3] + bv.w);
                }
            }
        }
    }
}

// ---------------------------------------------------------------------------
// Fused attention: one block per (chunk, head). 256 threads.
// RoPE applied at load time (q: row 0 only; k: row j uses kpe[j%128]).
// Null k/v prepended as column j=0. Softmax over 257 columns.
// sim is 64 x SIMW; columns >= 257 may hold garbage from the last tile and
// are never read.
// ---------------------------------------------------------------------------
#define SIMW 324
#define ATTN_SMEM ((64*68 + 64*68 + 64*SIMW) * 4)

__global__ __launch_bounds__(256)
void attn_kernel(const float* __restrict__ Q, const float* __restrict__ Kb,
                 const float* __restrict__ Vb,
                 const float* __restrict__ qpe63,   // q_pos_emb row 63 (64 f)
                 const float* __restrict__ kpe,     // k_pos_emb (128 x 64)
                 const float* __restrict__ null_k,
                 const float* __restrict__ null_v,
                 float* __restrict__ O)
{
    extern __shared__ float sm[];
    float* qs  = sm;                  // [64][68]
    float* kvs = qs + 64 * 68;        // [64][68]
    float* sim = kvs + 64 * 68;       // [64][SIMW]

    const int c = blockIdx.x;         // chunk 0..255
    const int h = blockIdx.y;         // head  0..7
    const int t = threadIdx.x;
    const int ty = t >> 4, tx = t & 15;

    const float scale = 0.125f;       // 64^-0.5

    // ---- load q (scaled) ----
    for (int e = t; e < 64 * 64; e += 256) {
        int i = e >> 6, d = e & 63;
        qs[i * 68 + d] = Q[((size_t)(c * 64 + i)) * INNER + h * 64 + d] * scale;
    }
    __syncthreads();

    // ---- rope on q row 0 ----
    float nq0 = 0.f;
    if (t < 64) {
        int d = t;
        float v = qs[d];
        float p = (d < 32) ? -qs[d + 32] : qs[d - 32];
        float f = qpe63[d];
        nq0 = v * cosf(f) + p * sinf(f);
    }
    __syncthreads();
    if (t < 64) qs[t] = nq0;
    __syncthreads();

    // ---- sim = q @ k^T, tiled over j (5 tiles of 64, covering 257 cols) ----
    for (int jt = 0; jt < 5; jt++) {
        // load k tile (raw)
        for (int e = t; e < 64 * 64; e += 256) {
            int jj = e >> 6, d = e & 63;
            int j = jt * 64 + jj;
            float val = 0.f;
            if (j == 0)       val = null_k[h * 64 + d];
            else if (j < 257) val = Kb[((size_t)(c * 256 + j - 1)) * INNER + h * 64 + d];
            kvs[jj * 68 + d] = val;
        }
        __syncthreads();
        // rope in place (needs pair element -> stage in regs)
        float nv[16];
        {
            int q = 0;
            for (int e = t; e < 64 * 64; e += 256, q++) {
                int jj = e >> 6, d = e & 63;
                int j = jt * 64 + jj;
                float val = kvs[jj * 68 + d];
                if (j >= 1 && j < 257) {
                    int kr = (j - 1) & 127;
                    float f = kpe[kr * 64 + d];
                    float p = (d < 32) ? -kvs[jj * 68 + d + 32] : kvs[jj * 68 + d - 32];
                    val = val * cosf(f) + p * sinf(f);
                }
                nv[q] = val;
            }
        }
        __syncthreads();
        {
            int q = 0;
            for (int e = t; e < 64 * 64; e += 256, q++) {
                int jj = e >> 6, d = e & 63;
                kvs[jj * 68 + d] = nv[q];
            }
        }
        __syncthreads();

        // compute 64x64 sim tile: thread -> rows ty*4.., cols tx*4..
        float s[4][4];
        #pragma unroll
        for (int i = 0; i < 4; i++)
            #pragma unroll
            for (int j = 0; j < 4; j++) s[i][j] = 0.f;
        for (int d = 0; d < 64; d++) {
            float a[4], b[4];
            #pragma unroll
            for (int i = 0; i < 4; i++) a[i] = qs[(ty * 4 + i) * 68 + d];
            #pragma unroll
            for (int j = 0; j < 4; j++) b[j] = kvs[(tx * 4 + j) * 68 + d];
            #pragma unroll
            for (int i = 0; i < 4; i++)
                #pragma unroll
                for (int j = 0; j < 4; j++) s[i][j] = fmaf(a[i], b[j], s[i][j]);
        }
        #pragma unroll
        for (int i = 0; i < 4; i++)
            #pragma unroll
            for (int j = 0; j < 4; j++)
                sim[(ty * 4 + i) * SIMW + jt * 64 + tx * 4 + j] = s[i][j];
        __syncthreads();
    }

    // ---- softmax over 257 cols, warp-per-row-group ----
    {
        const int warp = t >> 5, lane = t & 31;
        for (int i = warp; i < 64; i += 8) {
            float* row = sim + i * SIMW;
            float mx = -1e30f;
            for (int j = lane; j < 257; j += 32) mx = fmaxf(mx, row[j]);
            #pragma unroll
            for (int o = 16; o; o >>= 1) mx = fmaxf(mx, __shfl_xor_sync(~0u, mx, o));
            float sum = 0.f;
            for (int j = lane; j < 257; j += 32) {
                float e = __expf(row[j] - mx);
                row[j] = e;
                sum += e;
            }
            #pragma unroll
            for (int o = 16; o; o >>= 1) sum += __shfl_xor_sync(~0u, sum, o);
            float inv = 1.f / sum;
            for (int j = lane; j < 257; j += 32) row[j] *= inv;
        }
    }
    __syncthreads();

    // ---- o = attn @ v ----
    float oacc[4][4];
    #pragma unroll
    for (int i = 0; i < 4; i++)
        #pragma unroll
        for (int j = 0; j < 4; j++) oacc[i][j] = 0.f;

    for (int jt = 0; jt < 5; jt++) {
        for (int e = t; e < 64 * 64; e += 256) {
            int jj = e >> 6, d = e & 63;
            int j = jt * 64 + jj;
            float val = 0.f;
            if (j == 0)       val = null_v[h * 64 + d];
            else if (j < 257) val = Vb[((size_t)(c * 256 + j - 1)) * INNER + h * 64 + d];
            kvs[jj * 68 + d] = val;
        }
        __syncthreads();

        const int jmax = (jt == 4) ? 1 : 64;   // tile 4 holds only j=256
        for (int jj = 0; jj < jmax; jj++) {
            int j = jt * 64 + jj;
            float a[4], b[4];
            #pragma unroll
            for (int i = 0; i < 4; i++) a[i] = sim[(ty * 4 + i) * SIMW + j];
            #pragma unroll
            for (int d = 0; d < 4; d++) b[d] = kvs[jj * 68 + tx * 4 + d];
            #pragma unroll
            for (int i = 0; i < 4; i++)
                #pragma unroll
                for (int d = 0; d < 4; d++)
                    oacc[i][d] = fmaf(a[i], b[d], oacc[i][d]);
        }
        __syncthreads();
    }

    #pragma unroll
    for (int i = 0; i < 4; i++)
        #pragma unroll
        for (int d = 0; d < 4; d++)
            O[((size_t)(c * 64 + ty * 4 + i)) * INNER + h * 64 + tx * 4 + d] = oacc[i][d];
}

// ---------------------------------------------------------------------------
// Zero the first 63 token rows of each batch
// ---------------------------------------------------------------------------
__global__ void zero_prefix_kernel(float* __restrict__ out)
{
    size_t idx = (size_t)blockIdx.x * 256 + threadIdx.x;
    const size_t total = (size_t)4 * 63 * 1024;
    if (idx < total) {
        size_t b   = idx / (63 * 1024);
        size_t rem = idx % (63 * 1024);
        out[b * (size_t)4096 * 1024 + rem] = 0.f;
    }
}

// ---------------------------------------------------------------------------
// Launch
// ---------------------------------------------------------------------------
extern "C" void kernel_launch(void* const* d_in, const int* in_sizes, int n_in,
                              void* d_out, int out_size)
{
    const float* x        = (const float*)d_in[0];
    const float* context  = (const float*)d_in[1];
    const float* q_pos    = (const float*)d_in[2];
    const float* k_pos    = (const float*)d_in[3];
    const float* Wq       = (const float*)d_in[4];
    const float* Wk       = (const float*)d_in[5];
    const float* Wv       = (const float*)d_in[6];
    const float* Wo       = (const float*)d_in[7];
    const float* bo       = (const float*)d_in[8];
    const float* null_k   = (const float*)d_in[9];
    const float* null_v   = (const float*)d_in[10];
    float* out            = (float*)d_out;

    float *Qb, *Kb, *Vb, *Ob;
    cudaGetSymbolAddress((void**)&Qb, g_Q);
    cudaGetSymbolAddress((void**)&Kb, g_K);
    cudaGetSymbolAddress((void**)&Vb, g_V);
    cudaGetSymbolAddress((void**)&Ob, g_O);

    // Q = shifted-x @ Wq
    {
        dim3 grid(INNER / GBN, MQ / GBM);
        sgemm_kernel<1, 0><<<grid, 256>>>(x, Wq, Qb, MQ, INNER, DIMM, nullptr);
    }
    // K = context @ Wk ; V = context @ Wv
    {
        dim3 grid(INNER / GBN, MKV / GBM);
        sgemm_kernel<0, 0><<<grid, 256>>>(context, Wk, Kb, MKV, INNER, DIMM, nullptr);
        sgemm_kernel<0, 0><<<grid, 256>>>(context, Wv, Vb, MKV, INNER, DIMM, nullptr);
    }
    // fused rope + attention
    {
        cudaFuncSetAttribute(attn_kernel,
                             cudaFuncAttributeMaxDynamicSharedMemorySize, ATTN_SMEM);
        dim3 grid(BK_CH, NH);
        attn_kernel<<<grid, 256, ATTN_SMEM>>>(Qb, Kb, Vb,
                                              q_pos + 63 * 64, k_pos,
                                              null_k, null_v, Ob);
    }
    // out = attn_out @ Wo + bo, scattered with +63 shift
    {
        dim3 grid(DIMM / GBN, MQ / GBM);
        sgemm_kernel<0, 1><<<grid, 256>>>(Ob, Wo, out, MQ, DIMM, INNER, bo);
    }
    // zero first 63 rows per batch
    {
        const int total = 4 * 63 * 1024;
        zero_prefix_kernel<<<(total + 255) / 256, 256>>>(out);
    }
}

// round 4
// speedup vs baseline: 1.7099x; 1.7099x over previous
#include <cuda_runtime.h>
#include <cuda_bf16.h>
#include <math.h>

// ---------------------------------------------------------------------------
// Problem constants
// ---------------------------------------------------------------------------
#define DIMM   1024
#define INNER  512
#define BK_CH  256
#define CSZ    64
#define LKV    256
#define NH     8
#define DHD    64
#define MQ     (BK_CH*CSZ)      // 16384
#define MKV    (BK_CH*LKV)      // 65536

// ---------------------------------------------------------------------------
// Scratch
// ---------------------------------------------------------------------------
__device__ float g_Q[(size_t)MQ * INNER];
__device__ float g_K[(size_t)MKV * INNER];
__device__ float g_V[(size_t)MKV * INNER];
__device__ float g_O[(size_t)MQ * INNER];

// ---------------------------------------------------------------------------
// tf32 helpers
// ---------------------------------------------------------------------------
__device__ __forceinline__ unsigned f2tf(float f) {
    unsigned u;
    asm("cvt.rna.tf32.f32 %0, %1;" : "=r"(u) : "f"(f));
    return u;
}

__device__ __forceinline__ void mma_tf32(float* c, const unsigned* a, const unsigned* b) {
    asm volatile(
        "mma.sync.aligned.m16n8k8.row.col.f32.tf32.tf32.f32 "
        "{%0,%1,%2,%3}, {%4,%5,%6,%7}, {%8,%9}, {%0,%1,%2,%3};\n"
        : "+f"(c[0]), "+f"(c[1]), "+f"(c[2]), "+f"(c[3])
        : "r"(a[0]), "r"(a[1]), "r"(a[2]), "r"(a[3]),
          "r"(b[0]), "r"(b[1]));
}

// ---------------------------------------------------------------------------
// TF32 tensor-core GEMM: C[M,N] = A[M,K] @ W[K,N]
// BM=128, BN=128, BK=16, 256 threads (8 warps, 2x4), warp tile 64x32.
// GATHER==1: A row gm reads A[(gm+63)*K] if (gm%4096)<4033 else zeros.
// EPI==1: scatter row gm -> C[b*4096 + (gm%4096)+63] (+bias) if pos<4033.
// ---------------------------------------------------------------------------
#define TBM 128
#define TBN 128
#define TBK 16

template<int GATHER, int EPI>
__global__ __launch_bounds__(256)
void tf32_gemm(const float* __restrict__ A, const float* __restrict__ W,
               float* __restrict__ C, int M, int N, int K,
               const float* __restrict__ bias)
{
    __shared__ unsigned As[TBK][133];   // tf32 bits, k-major (transposed)
    __shared__ unsigned Bs[TBK][132];   // tf32 bits, k-major

    const int n0 = blockIdx.x * TBN;
    const int m0 = blockIdx.y * TBM;
    const int t  = threadIdx.x;
    const int lane = t & 31;
    const int warp = t >> 5;
    const int wm = warp >> 2;           // 0..1
    const int wn = warp & 3;            // 0..3
    const int m_base = wm * 64;
    const int n_base = wn * 32;
    const int lg = lane >> 2;           // 0..7
    const int lk = lane & 3;            // 0..3

    // global A load mapping: thread -> (row t>>1, cols (t&1)*8 .. +7)
    const int arow  = t >> 1;
    const int acolg = (t & 1) * 8;
    // global B load mapping: thread -> (row t>>4, cols (t&15)*8 .. +7)
    const int brow  = t >> 4;
    const int bcolg = (t & 15) * 8;

    // resolve A row pointer (with shifted-x gather)
    const float* Aptr;
    bool avalid = true;
    {
        int gm = m0 + arow;
        if (GATHER == 1) {
            int pos = gm & 4095;
            if (pos < 4033) {
                Aptr = A + (size_t)(gm + 63) * K;
            } else {
                Aptr = A;
                avalid = false;
            }
        } else {
            Aptr = A + (size_t)gm * K;
        }
    }
    const float* Wptr = W + (size_t)brow * N + n0 + bcolg;

    float acc[4][4][4];
    #pragma unroll
    for (int i = 0; i < 4; i++)
        #pragma unroll
        for (int j = 0; j < 4; j++)
            #pragma unroll
            for (int q = 0; q < 4; q++) acc[i][j][q] = 0.f;

    // prologue load
    float4 av0 = make_float4(0,0,0,0), av1 = make_float4(0,0,0,0);
    float4 bv0, bv1;
    if (avalid) {
        av0 = *(const float4*)(Aptr + acolg);
        av1 = *(const float4*)(Aptr + acolg + 4);
    }
    bv0 = *(const float4*)(Wptr);
    bv1 = *(const float4*)(Wptr + 4);

    for (int k0 = 0; k0 < K; k0 += TBK) {
        // store current regs -> smem (cvt to tf32)
        As[acolg + 0][arow] = f2tf(av0.x);
        As[acolg + 1][arow] = f2tf(av0.y);
        As[acolg + 2][arow] = f2tf(av0.z);
        As[acolg + 3][arow] = f2tf(av0.w);
        As[acolg + 4][arow] = f2tf(av1.x);
        As[acolg + 5][arow] = f2tf(av1.y);
        As[acolg + 6][arow] = f2tf(av1.z);
        As[acolg + 7][arow] = f2tf(av1.w);
        {
            uint4 u0 = make_uint4(f2tf(bv0.x), f2tf(bv0.y), f2tf(bv0.z), f2tf(bv0.w));
            uint4 u1 = make_uint4(f2tf(bv1.x), f2tf(bv1.y), f2tf(bv1.z), f2tf(bv1.w));
            *(uint4*)&Bs[brow][bcolg]     = u0;
            *(uint4*)&Bs[brow][bcolg + 4] = u1;
        }
        __syncthreads();

        // prefetch next iteration's globals (overlaps with mma stage)
        int kn = k0 + TBK;
        if (kn < K) {
            if (avalid) {
                av0 = *(const float4*)(Aptr + kn + acolg);
                av1 = *(const float4*)(Aptr + kn + acolg + 4);
            }
            bv0 = *(const float4*)(Wptr + (size_t)kn * N);
            bv1 = *(const float4*)(Wptr + (size_t)kn * N + 4);
        }

        // two k-chunks of 8
        #pragma unroll
        for (int kk0 = 0; kk0 < TBK; kk0 += 8) {
            unsigned afr[4][4], bfr[4][2];
            const int kA = kk0 + lk;
            #pragma unroll
            for (int i = 0; i < 4; i++) {
                const int mrow = m_base + i * 16 + lg;
                afr[i][0] = As[kA][mrow];
                afr[i][1] = As[kA][mrow + 8];
                afr[i][2] = As[kA + 4][mrow];
                afr[i][3] = As[kA + 4][mrow + 8];
            }
            #pragma unroll
            for (int j = 0; j < 4; j++) {
                const int ncol = n_base + j * 8 + lg;
                bfr[j][0] = Bs[kA][ncol];
                bfr[j][1] = Bs[kA + 4][ncol];
            }
            #pragma unroll
            for (int i = 0; i < 4; i++)
                #pragma unroll
                for (int j = 0; j < 4; j++)
                    mma_tf32(acc[i][j], afr[i], bfr[j]);
        }
        __syncthreads();
    }

    // epilogue
    #pragma unroll
    for (int i = 0; i < 4; i++) {
        const int r0 = m0 + m_base + i * 16 + lg;
        const int r1 = r0 + 8;
        #pragma unroll
        for (int j = 0; j < 4; j++) {
            const int col = n0 + n_base + j * 8 + (lk << 1);
            if (EPI == 0) {
                *(float2*)(C + (size_t)r0 * N + col) = make_float2(acc[i][j][0], acc[i][j][1]);
                *(float2*)(C + (size_t)r1 * N + col) = make_float2(acc[i][j][2], acc[i][j][3]);
            } else {
                const float2 bvv = *(const float2*)(bias + col);
                int pos0 = r0 & 4095;
                if (pos0 < 4033) {
                    const int bb = r0 >> 12;
                    float* p = C + ((size_t)bb * 4096 + pos0 + 63) * N + col;
                    *(float2*)p = make_float2(acc[i][j][0] + bvv.x, acc[i][j][1] + bvv.y);
                }
                int pos1 = r1 & 4095;
                if (pos1 < 4033) {
                    const int bb = r1 >> 12;
                    float* p = C + ((size_t)bb * 4096 + pos1 + 63) * N + col;
                    *(float2*)p = make_float2(acc[i][j][2] + bvv.x, acc[i][j][3] + bvv.y);
                }
            }
        }
    }
}

// ---------------------------------------------------------------------------
// Fused attention (unchanged — passed in round 2)
// ---------------------------------------------------------------------------
#define SIMW 324
#define ATTN_SMEM ((64*68 + 64*68 + 64*SIMW) * 4)

__global__ __launch_bounds__(256)
void attn_kernel(const float* __restrict__ Q, const float* __restrict__ Kb,
                 const float* __restrict__ Vb,
                 const float* __restrict__ qpe63,
                 const float* __restrict__ kpe,
                 const float* __restrict__ null_k,
                 const float* __restrict__ null_v,
                 float* __restrict__ O)
{
    extern __shared__ float sm[];
    float* qs  = sm;                  // [64][68]
    float* kvs = qs + 64 * 68;        // [64][68]
    float* sim = kvs + 64 * 68;       // [64][SIMW]

    const int c = blockIdx.x;
    const int h = blockIdx.y;
    const int t = threadIdx.x;
    const int ty = t >> 4, tx = t & 15;

    const float scale = 0.125f;

    for (int e = t; e < 64 * 64; e += 256) {
        int i = e >> 6, d = e & 63;
        qs[i * 68 + d] = Q[((size_t)(c * 64 + i)) * INNER + h * 64 + d] * scale;
    }
    __syncthreads();

    float nq0 = 0.f;
    if (t < 64) {
        int d = t;
        float v = qs[d];
        float p = (d < 32) ? -qs[d + 32] : qs[d - 32];
        float f = qpe63[d];
        nq0 = v * cosf(f) + p * sinf(f);
    }
    __syncthreads();
    if (t < 64) qs[t] = nq0;
    __syncthreads();

    for (int jt = 0; jt < 5; jt++) {
        for (int e = t; e < 64 * 64; e += 256) {
            int jj = e >> 6, d = e & 63;
            int j = jt * 64 + jj;
            float val = 0.f;
            if (j == 0)       val = null_k[h * 64 + d];
            else if (j < 257) val = Kb[((size_t)(c * 256 + j - 1)) * INNER + h * 64 + d];
            kvs[jj * 68 + d] = val;
        }
        __syncthreads();
        float nv[16];
        {
            int q = 0;
            for (int e = t; e < 64 * 64; e += 256, q++) {
                int jj = e >> 6, d = e & 63;
                int j = jt * 64 + jj;
                float val = kvs[jj * 68 + d];
                if (j >= 1 && j < 257) {
                    int kr = (j - 1) & 127;
                    float f = kpe[kr * 64 + d];
                    float p = (d < 32) ? -kvs[jj * 68 + d + 32] : kvs[jj * 68 + d - 32];
                    val = val * cosf(f) + p * sinf(f);
                }
                nv[q] = val;
            }
        }
        __syncthreads();
        {
            int q = 0;
            for (int e = t; e < 64 * 64; e += 256, q++) {
                int jj = e >> 6, d = e & 63;
                kvs[jj * 68 + d] = nv[q];
            }
        }
        __syncthreads();

        float s[4][4];
        #pragma unroll
        for (int i = 0; i < 4; i++)
            #pragma unroll
            for (int j = 0; j < 4; j++) s[i][j] = 0.f;
        for (int d = 0; d < 64; d++) {
            float a[4], b[4];
            #pragma unroll
            for (int i = 0; i < 4; i++) a[i] = qs[(ty * 4 + i) * 68 + d];
            #pragma unroll
            for (int j = 0; j < 4; j++) b[j] = kvs[(tx * 4 + j) * 68 + d];
            #pragma unroll
            for (int i = 0; i < 4; i++)
                #pragma unroll
                for (int j = 0; j < 4; j++) s[i][j] = fmaf(a[i], b[j], s[i][j]);
        }
        #pragma unroll
        for (int i = 0; i < 4; i++)
            #pragma unroll
            for (int j = 0; j < 4; j++)
                sim[(ty * 4 + i) * SIMW + jt * 64 + tx * 4 + j] = s[i][j];
        __syncthreads();
    }

    {
        const int warp = t >> 5, lane = t & 31;
        for (int i = warp; i < 64; i += 8) {
            float* row = sim + i * SIMW;
            float mx = -1e30f;
            for (int j = lane; j < 257; j += 32) mx = fmaxf(mx, row[j]);
            #pragma unroll
            for (int o = 16; o; o >>= 1) mx = fmaxf(mx, __shfl_xor_sync(~0u, mx, o));
            float sum = 0.f;
            for (int j = lane; j < 257; j += 32) {
                float e = __expf(row[j] - mx);
                row[j] = e;
                sum += e;
            }
            #pragma unroll
            for (int o = 16; o; o >>= 1) sum += __shfl_xor_sync(~0u, sum, o);
            float inv = 1.f / sum;
            for (int j = lane; j < 257; j += 32) row[j] *= inv;
        }
    }
    __syncthreads();

    float oacc[4][4];
    #pragma unroll
    for (int i = 0; i < 4; i++)
        #pragma unroll
        for (int j = 0; j < 4; j++) oacc[i][j] = 0.f;

    for (int jt = 0; jt < 5; jt++) {
        for (int e = t; e < 64 * 64; e += 256) {
            int jj = e >> 6, d = e & 63;
            int j = jt * 64 + jj;
            float val = 0.f;
            if (j == 0)       val = null_v[h * 64 + d];
            else if (j < 257) val = Vb[((size_t)(c * 256 + j - 1)) * INNER + h * 64 + d];
            kvs[jj * 68 + d] = val;
        }
        __syncthreads();

        const int jmax = (jt == 4) ? 1 : 64;
        for (int jj = 0; jj < jmax; jj++) {
            int j = jt * 64 + jj;
            float a[4], b[4];
            #pragma unroll
            for (int i = 0; i < 4; i++) a[i] = sim[(ty * 4 + i) * SIMW + j];
            #pragma unroll
            for (int d = 0; d < 4; d++) b[d] = kvs[jj * 68 + tx * 4 + d];
            #pragma unroll
            for (int i = 0; i < 4; i++)
                #pragma unroll
                for (int d = 0; d < 4; d++)
                    oacc[i][d] = fmaf(a[i], b[d], oacc[i][d]);
        }
        __syncthreads();
    }

    #pragma unroll
    for (int i = 0; i < 4; i++)
        #pragma unroll
        for (int d = 0; d < 4; d++)
            O[((size_t)(c * 64 + ty * 4 + i)) * INNER + h * 64 + tx * 4 + d] = oacc[i][d];
}

// ---------------------------------------------------------------------------
// Zero the first 63 token rows of each batch
// ---------------------------------------------------------------------------
__global__ void zero_prefix_kernel(float* __restrict__ out)
{
    size_t idx = (size_t)blockIdx.x * 256 + threadIdx.x;
    const size_t total = (size_t)4 * 63 * 1024;
    if (idx < total) {
        size_t b   = idx / (63 * 1024);
        size_t rem = idx % (63 * 1024);
        out[b * (size_t)4096 * 1024 + rem] = 0.f;
    }
}

// ---------------------------------------------------------------------------
// Launch
// ---------------------------------------------------------------------------
extern "C" void kernel_launch(void* const* d_in, const int* in_sizes, int n_in,
                              void* d_out, int out_size)
{
    const float* x        = (const float*)d_in[0];
    const float* context  = (const float*)d_in[1];
    const float* q_pos    = (const float*)d_in[2];
    const float* k_pos    = (const float*)d_in[3];
    const float* Wq       = (const float*)d_in[4];
    const float* Wk       = (const float*)d_in[5];
    const float* Wv       = (const float*)d_in[6];
    const float* Wo       = (const float*)d_in[7];
    const float* bo       = (const float*)d_in[8];
    const float* null_k   = (const float*)d_in[9];
    const float* null_v   = (const float*)d_in[10];
    float* out            = (float*)d_out;

    float *Qb, *Kb, *Vb, *Ob;
    cudaGetSymbolAddress((void**)&Qb, g_Q);
    cudaGetSymbolAddress((void**)&Kb, g_K);
    cudaGetSymbolAddress((void**)&Vb, g_V);
    cudaGetSymbolAddress((void**)&Ob, g_O);

    // Q = shifted-x @ Wq
    {
        dim3 grid(INNER / TBN, MQ / TBM);
        tf32_gemm<1, 0><<<grid, 256>>>(x, Wq, Qb, MQ, INNER, DIMM, nullptr);
    }
    // K = context @ Wk ; V = context @ Wv
    {
        dim3 grid(INNER / TBN, MKV / TBM);
        tf32_gemm<0, 0><<<grid, 256>>>(context, Wk, Kb, MKV, INNER, DIMM, nullptr);
        tf32_gemm<0, 0><<<grid, 256>>>(context, Wv, Vb, MKV, INNER, DIMM, nullptr);
    }
    // fused rope + attention
    {
        cudaFuncSetAttribute(attn_kernel,
                             cudaFuncAttributeMaxDynamicSharedMemorySize, ATTN_SMEM);
        dim3 grid(BK_CH, NH);
        attn_kernel<<<grid, 256, ATTN_SMEM>>>(Qb, Kb, Vb,
                                              q_pos + 63 * 64, k_pos,
                                              null_k, null_v, Ob);
    }
    // out = attn_out @ Wo + bo, scattered with +63 shift
    {
        dim3 grid(DIMM / TBN, MQ / TBM);
        tf32_gemm<0, 1><<<grid, 256>>>(Ob, Wo, out, MQ, DIMM, INNER, bo);
    }
    // zero first 63 rows per batch
    {
        const int total = 4 * 63 * 1024;
        zero_prefix_kernel<<<(total + 255) / 256, 256>>>(out);
    }
}

// round 6
// speedup vs baseline: 2.1272x; 1.2441x over previous
#include <cuda_runtime.h>
#include <cuda_bf16.h>
#include <math.h>
#include <stdint.h>

// ---------------------------------------------------------------------------
// Problem constants
// ---------------------------------------------------------------------------
#define DIMM   1024
#define INNER  512
#define BK_CH  256
#define NH     8
#define MQ     (BK_CH*64)       // 16384
#define MKV    (BK_CH*256)      // 65536

// ---------------------------------------------------------------------------
// Scratch
// ---------------------------------------------------------------------------
__device__ float g_Q[(size_t)MQ * INNER];
__device__ float g_K[(size_t)MKV * INNER];
__device__ float g_V[(size_t)MKV * INNER];
__device__ float g_O[(size_t)MQ * INNER];

// ---------------------------------------------------------------------------
// helpers
// ---------------------------------------------------------------------------
__device__ __forceinline__ uint32_t smem_u32(const void* p) {
    uint32_t a;
    asm("{ .reg .u64 t; cvta.to.shared.u64 t, %1; cvt.u32.u64 %0, t; }" : "=r"(a) : "l"(p));
    return a;
}
__device__ __forceinline__ unsigned f2tf(float f) {
    unsigned u; asm("cvt.rna.tf32.f32 %0, %1;" : "=r"(u) : "f"(f)); return u;
}
__device__ __forceinline__ void mma_tf32(float* c, const unsigned* a, const unsigned* b) {
    asm volatile(
        "mma.sync.aligned.m16n8k8.row.col.f32.tf32.tf32.f32 "
        "{%0,%1,%2,%3}, {%4,%5,%6,%7}, {%8,%9}, {%0,%1,%2,%3};\n"
        : "+f"(c[0]), "+f"(c[1]), "+f"(c[2]), "+f"(c[3])
        : "r"(a[0]), "r"(a[1]), "r"(a[2]), "r"(a[3]),
          "r"(b[0]), "r"(b[1]));
}
__device__ __forceinline__ void cpa16(uint32_t dst, const void* src, uint32_t ssize) {
    asm volatile("cp.async.cg.shared.global [%0], [%1], 16, %2;"
                 :: "r"(dst), "l"(src), "r"(ssize) : "memory");
}
#define CPA_COMMIT() asm volatile("cp.async.commit_group;" ::: "memory")
#define CPA_WAIT1()  asm volatile("cp.async.wait_group 1;" ::: "memory")

// ---------------------------------------------------------------------------
// TF32 GEMM with cp.async 3-stage pipeline: C[M,N] = A[M,K] @ W[K,N]
// BM=128, BN=128, BK=16; 256 threads (8 warps 2x4), warp tile 64x32.
// A in smem [m][k] stride 20 (raw fp32), B in smem [k][n] stride 136.
// cvt to tf32 at fragment-load time.
// ---------------------------------------------------------------------------
#define STAGES    3
#define AS_STRIDE 20
#define BS_STRIDE 136
#define A_STAGE_F (128*AS_STRIDE)            // 2560 floats
#define B_STAGE_F (16*BS_STRIDE)             // 2176 floats
#define STAGE_F   (A_STAGE_F + B_STAGE_F)    // 4736 floats
#define GEMM_SMEM (STAGES * STAGE_F * 4)     // 56832 bytes

template<int GATHER, int EPI>
__global__ __launch_bounds__(256)
void tf32_gemm(const float* __restrict__ A, const float* __restrict__ W,
               float* __restrict__ C, int M, int N, int K,
               const float* __restrict__ bias)
{
    extern __shared__ float smf[];
    const uint32_t sbase = smem_u32(smf);

    const int n0 = blockIdx.x * 128;
    const int m0 = blockIdx.y * 128;
    const int t  = threadIdx.x;
    const int lane = t & 31;
    const int warp = t >> 5;
    const int wm = warp >> 2;           // 0..1
    const int wn = warp & 3;            // 0..3
    const int m_base = wm * 64;
    const int n_base = wn * 32;
    const int lg = lane >> 2;           // 0..7
    const int lk = lane & 3;            // 0..3
    const int kt = K / 16;

    // A loader: row r = t>>1, cols (t&1)*8 + {0,4}
    const int arow  = t >> 1;
    const int acol0 = (t & 1) * 8;
    const float* Aptr; uint32_t asz = 16;
    {
        int gm = m0 + arow;
        if (GATHER == 1) {
            int pos = gm & 4095;
            if (pos < 4033) Aptr = A + (size_t)(gm + 63) * K;
            else { Aptr = A; asz = 0; }
        } else Aptr = A + (size_t)gm * K;
    }
    // B loader: row kr = t>>4, cols (t&15)*8 + {0,4}
    const int bkr   = t >> 4;
    const int bcol0 = (t & 15) * 8;
    const float* Wptr = W + (size_t)bkr * N + n0 + bcol0;

    auto load_stage = [&](int i) {
        const int buf = i % STAGES;
        const int k0  = i * 16;
        const uint32_t sb = sbase + buf * (STAGE_F * 4);
        cpa16(sb + (arow * AS_STRIDE + acol0) * 4,     Aptr + k0 + acol0,     asz);
        cpa16(sb + (arow * AS_STRIDE + acol0 + 4) * 4, Aptr + k0 + acol0 + 4, asz);
        const uint32_t bb = sb + A_STAGE_F * 4;
        cpa16(bb + (bkr * BS_STRIDE + bcol0) * 4,     Wptr + (size_t)k0 * N,     16);
        cpa16(bb + (bkr * BS_STRIDE + bcol0 + 4) * 4, Wptr + (size_t)k0 * N + 4, 16);
    };

    float acc[4][4][4];
    #pragma unroll
    for (int i = 0; i < 4; i++)
        #pragma unroll
        for (int j = 0; j < 4; j++)
            #pragma unroll
            for (int q = 0; q < 4; q++) acc[i][j][q] = 0.f;

    // prologue: stages 0..STAGES-2
    #pragma unroll
    for (int s = 0; s < STAGES - 1; s++) { load_stage(s); CPA_COMMIT(); }

    for (int i = 0; i < kt; i++) {
        CPA_WAIT1();
        __syncthreads();

        // issue next stage into the buffer freed at iter i-1
        if (i + STAGES - 1 < kt) load_stage(i + STAGES - 1);
        CPA_COMMIT();

        const float* As = smf + (i % STAGES) * STAGE_F;
        const float* Bs = As + A_STAGE_F;

        #pragma unroll
        for (int kk0 = 0; kk0 < 16; kk0 += 8) {
            const int kA = kk0 + lk;
            unsigned afr[4][4], bfr[4][2];
            #pragma unroll
            for (int ii = 0; ii < 4; ii++) {
                const int mrow = m_base + ii * 16 + lg;
                afr[ii][0] = f2tf(As[mrow * AS_STRIDE + kA]);
                afr[ii][1] = f2tf(As[(mrow + 8) * AS_STRIDE + kA]);
                afr[ii][2] = f2tf(As[mrow * AS_STRIDE + kA + 4]);
                afr[ii][3] = f2tf(As[(mrow + 8) * AS_STRIDE + kA + 4]);
            }
            #pragma unroll
            for (int j = 0; j < 4; j++) {
                const int ncol = n_base + j * 8 + lg;
                bfr[j][0] = f2tf(Bs[kA * BS_STRIDE + ncol]);
                bfr[j][1] = f2tf(Bs[(kA + 4) * BS_STRIDE + ncol]);
            }
            #pragma unroll
            for (int ii = 0; ii < 4; ii++)
                #pragma unroll
                for (int j = 0; j < 4; j++)
                    mma_tf32(acc[ii][j], afr[ii], bfr[j]);
        }
        __syncthreads();
    }

    // epilogue (identical to the round-4 version that passed)
    #pragma unroll
    for (int i = 0; i < 4; i++) {
        const int r0 = m0 + m_base + i * 16 + lg;
        const int r1 = r0 + 8;
        #pragma unroll
        for (int j = 0; j < 4; j++) {
            const int col = n0 + n_base + j * 8 + (lk << 1);
            if (EPI == 0) {
                *(float2*)(C + (size_t)r0 * N + col) = make_float2(acc[i][j][0], acc[i][j][1]);
                *(float2*)(C + (size_t)r1 * N + col) = make_float2(acc[i][j][2], acc[i][j][3]);
            } else {
                const float2 bvv = *(const float2*)(bias + col);
                int pos0 = r0 & 4095;
                if (pos0 < 4033) {
                    const int bb = r0 >> 12;
                    float* p = C + ((size_t)bb * 4096 + pos0 + 63) * N + col;
                    *(float2*)p = make_float2(acc[i][j][0] + bvv.x, acc[i][j][1] + bvv.y);
                }
                int pos1 = r1 & 4095;
                if (pos1 < 4033) {
                    const int bb = r1 >> 12;
                    float* p = C + ((size_t)bb * 4096 + pos1 + 63) * N + col;
                    *(float2*)p = make_float2(acc[i][j][2] + bvv.x, acc[i][j][3] + bvv.y);
                }
            }
        }
    }
}

// ---------------------------------------------------------------------------
// Fused attention v2: one block per (chunk, head, half). 32 q-rows per block.
// smem ~66KB -> 3 CTAs/SM.
// ---------------------------------------------------------------------------
#define SIMW 324
#define ATTN_SMEM ((32*68 + 64*68 + 32*SIMW) * 4)

__global__ __launch_bounds__(256)
void attn_kernel(const float* __restrict__ Q, const float* __restrict__ Kb,
                 const float* __restrict__ Vb,
                 const float* __restrict__ qpe63,
                 const float* __restrict__ kpe,
                 const float* __restrict__ null_k,
                 const float* __restrict__ null_v,
                 float* __restrict__ O)
{
    extern __shared__ float sm[];
    float* qs  = sm;                  // [32][68]
    float* kvs = qs + 32 * 68;        // [64][68]
    float* sim = kvs + 64 * 68;       // [32][SIMW]

    const int c    = blockIdx.x;
    const int h    = blockIdx.y;
    const int half = blockIdx.z;      // 0/1 -> q rows 0..31 / 32..63
    const int r0   = half * 32;
    const int t    = threadIdx.x;
    const int ty = t >> 4, tx = t & 15;
    const float scale = 0.125f;

    // load q (scaled): 32 rows
    for (int e = t; e < 32 * 64; e += 256) {
        int i = e >> 6, d = e & 63;
        qs[i * 68 + d] = Q[((size_t)(c * 64 + r0 + i)) * INNER + h * 64 + d] * scale;
    }
    __syncthreads();

    // rope on chunk-row 0 (only in half 0)
    if (half == 0) {
        float nq0 = 0.f;
        if (t < 64) {
            int d = t;
            float v = qs[d];
            float p = (d < 32) ? -qs[d + 32] : qs[d - 32];
            float f = qpe63[d];
            nq0 = v * cosf(f) + p * sinf(f);
        }
        __syncthreads();
        if (t < 64) qs[t] = nq0;
        __syncthreads();
    }

    // sim = q @ k^T over 5 j-tiles of 64
    for (int jt = 0; jt < 5; jt++) {
        for (int e = t; e < 64 * 64; e += 256) {
            int jj = e >> 6, d = e & 63;
            int j = jt * 64 + jj;
            float val = 0.f;
            if (j == 0)       val = null_k[h * 64 + d];
            else if (j < 257) val = Kb[((size_t)(c * 256 + j - 1)) * INNER + h * 64 + d];
            kvs[jj * 68 + d] = val;
        }
        __syncthreads();
        float nv[16];
        {
            int q = 0;
            for (int e = t; e < 64 * 64; e += 256, q++) {
                int jj = e >> 6, d = e & 63;
                int j = jt * 64 + jj;
                float val = kvs[jj * 68 + d];
                if (j >= 1 && j < 257) {
                    int kr = (j - 1) & 127;
                    float f = kpe[kr * 64 + d];
                    float p = (d < 32) ? -kvs[jj * 68 + d + 32] : kvs[jj * 68 + d - 32];
                    val = val * cosf(f) + p * sinf(f);
                }
                nv[q] = val;
            }
        }
        __syncthreads();
        {
            int q = 0;
            for (int e = t; e < 64 * 64; e += 256, q++) {
                int jj = e >> 6, d = e & 63;
                kvs[jj * 68 + d] = nv[q];
            }
        }
        __syncthreads();

        // 32x64 sim tile: thread -> rows ty*2+{0,1}, cols tx*4..
        float s[2][4];
        #pragma unroll
        for (int i = 0; i < 2; i++)
            #pragma unroll
            for (int j = 0; j < 4; j++) s[i][j] = 0.f;
        for (int d = 0; d < 64; d++) {
            float a[2], b[4];
            #pragma unroll
            for (int i = 0; i < 2; i++) a[i] = qs[(ty * 2 + i) * 68 + d];
            #pragma unroll
            for (int j = 0; j < 4; j++) b[j] = kvs[(tx * 4 + j) * 68 + d];
            #pragma unroll
            for (int i = 0; i < 2; i++)
                #pragma unroll
                for (int j = 0; j < 4; j++) s[i][j] = fmaf(a[i], b[j], s[i][j]);
        }
        #pragma unroll
        for (int i = 0; i < 2; i++)
            #pragma unroll
            for (int j = 0; j < 4; j++)
                sim[(ty * 2 + i) * SIMW + jt * 64 + tx * 4 + j] = s[i][j];
        __syncthreads();
    }

    // softmax over 257 cols (32 rows, 8 warps x 4 rows)
    {
        const int warp = t >> 5, lanei = t & 31;
        for (int i = warp; i < 32; i += 8) {
            float* row = sim + i * SIMW;
            float mx = -1e30f;
            for (int j = lanei; j < 257; j += 32) mx = fmaxf(mx, row[j]);
            #pragma unroll
            for (int o = 16; o; o >>= 1) mx = fmaxf(mx, __shfl_xor_sync(~0u, mx, o));
            float sum = 0.f;
            for (int j = lanei; j < 257; j += 32) {
                float e = __expf(row[j] - mx);
                row[j] = e;
                sum += e;
            }
            #pragma unroll
            for (int o = 16; o; o >>= 1) sum += __shfl_xor_sync(~0u, sum, o);
            float inv = 1.f / sum;
            for (int j = lanei; j < 257; j += 32) row[j] *= inv;
        }
    }
    __syncthreads();

    // o = attn @ v
    float oacc[2][4];
    #pragma unroll
    for (int i = 0; i < 2; i++)
        #pragma unroll
        for (int j = 0; j < 4; j++) oacc[i][j] = 0.f;

    for (int jt = 0; jt < 5; jt++) {
        for (int e = t; e < 64 * 64; e += 256) {
            int jj = e >> 6, d = e & 63;
            int j = jt * 64 + jj;
            float val = 0.f;
            if (j == 0)       val = null_v[h * 64 + d];
            else if (j < 257) val = Vb[((size_t)(c * 256 + j - 1)) * INNER + h * 64 + d];
            kvs[jj * 68 + d] = val;
        }
        __syncthreads();

        const int jmax = (jt == 4) ? 1 : 64;
        for (int jj = 0; jj < jmax; jj++) {
            int j = jt * 64 + jj;
            float a[2], b[4];
            #pragma unroll
            for (int i = 0; i < 2; i++) a[i] = sim[(ty * 2 + i) * SIMW + j];
            #pragma unroll
            for (int d = 0; d < 4; d++) b[d] = kvs[jj * 68 + tx * 4 + d];
            #pragma unroll
            for (int i = 0; i < 2; i++)
                #pragma unroll
                for (int d = 0; d < 4; d++)
                    oacc[i][d] = fmaf(a[i], b[d], oacc[i][d]);
        }
        __syncthreads();
    }

    #pragma unroll
    for (int i = 0; i < 2; i++)
        #pragma unroll
        for (int d = 0; d < 4; d++)
            O[((size_t)(c * 64 + r0 + ty * 2 + i)) * INNER + h * 64 + tx * 4 + d] = oacc[i][d];
}

// ---------------------------------------------------------------------------
// Zero the first 63 token rows of each batch
// ---------------------------------------------------------------------------
__global__ void zero_prefix_kernel(float* __restrict__ out)
{
    size_t idx = (size_t)blockIdx.x * 256 + threadIdx.x;
    const size_t total = (size_t)4 * 63 * 1024;
    if (idx < total) {
        size_t b   = idx / (63 * 1024);
        size_t rem = idx % (63 * 1024);
        out[b * (size_t)4096 * 1024 + rem] = 0.f;
    }
}

// ---------------------------------------------------------------------------
// Launch
// ---------------------------------------------------------------------------
extern "C" void kernel_launch(void* const* d_in, const int* in_sizes, int n_in,
                              void* d_out, int out_size)
{
    const float* x        = (const float*)d_in[0];
    const float* context  = (const float*)d_in[1];
    const float* q_pos    = (const float*)d_in[2];
    const float* k_pos    = (const float*)d_in[3];
    const float* Wq       = (const float*)d_in[4];
    const float* Wk       = (const float*)d_in[5];
    const float* Wv       = (const float*)d_in[6];
    const float* Wo       = (const float*)d_in[7];
    const float* bo       = (const float*)d_in[8];
    const float* null_k   = (const float*)d_in[9];
    const float* null_v   = (const float*)d_in[10];
    float* out            = (float*)d_out;

    float *Qb, *Kb, *Vb, *Ob;
    cudaGetSymbolAddress((void**)&Qb, g_Q);
    cudaGetSymbolAddress((void**)&Kb, g_K);
    cudaGetSymbolAddress((void**)&Vb, g_V);
    cudaGetSymbolAddress((void**)&Ob, g_O);

    cudaFuncSetAttribute(tf32_gemm<1,0>, cudaFuncAttributeMaxDynamicSharedMemorySize, GEMM_SMEM);
    cudaFuncSetAttribute(tf32_gemm<0,0>, cudaFuncAttributeMaxDynamicSharedMemorySize, GEMM_SMEM);
    cudaFuncSetAttribute(tf32_gemm<0,1>, cudaFuncAttributeMaxDynamicSharedMemorySize, GEMM_SMEM);
    cudaFuncSetAttribute(attn_kernel, cudaFuncAttributeMaxDynamicSharedMemorySize, ATTN_SMEM);

    // Q = shifted-x @ Wq
    {
        dim3 grid(INNER / 128, MQ / 128);
        tf32_gemm<1, 0><<<grid, 256, GEMM_SMEM>>>(x, Wq, Qb, MQ, INNER, DIMM, nullptr);
    }
    // K = context @ Wk ; V = context @ Wv
    {
        dim3 grid(INNER / 128, MKV / 128);
        tf32_gemm<0, 0><<<grid, 256, GEMM_SMEM>>>(context, Wk, Kb, MKV, INNER, DIMM, nullptr);
        tf32_gemm<0, 0><<<grid, 256, GEMM_SMEM>>>(context, Wv, Vb, MKV, INNER, DIMM, nullptr);
    }
    // fused rope + attention
    {
        dim3 grid(BK_CH, NH, 2);
        attn_kernel<<<grid, 256, ATTN_SMEM>>>(Qb, Kb, Vb,
                                              q_pos + 63 * 64, k_pos,
                                              null_k, null_v, Ob);
    }
    // out = attn_out @ Wo + bo, scattered with +63 shift
    {
        dim3 grid(DIMM / 128, MQ / 128);
        tf32_gemm<0, 1><<<grid, 256, GEMM_SMEM>>>(Ob, Wo, out, MQ, DIMM, INNER, bo);
    }
    // zero first 63 rows per batch
    {
        const int total = 4 * 63 * 1024;
        zero_prefix_kernel<<<(total + 255) / 256, 256>>>(out);
    }
}